// round 9
// baseline (speedup 1.0000x reference)
#include <cuda_runtime.h>
#include <cuda_bf16.h>
#include <cstdint>

// ---------------------------------------------------------------------------
// GraphSAGE forward (round 9): two-level int8 IMMA chain.
// Fix vs round 8: aarch64 'char' is unsigned -> all quantized planes are
// 'signed char' (k_gemv was reading lo-plane bytes as unsigned).
// a ~ (rs/16256)(128*ah + al); A@W ~ rs*ws * (16384*HH + 128*X)/16256^2.
// CTA = 64m x 256n (full row) -> epilogue requantizes next layer's input.
// ---------------------------------------------------------------------------

typedef signed char s8;

constexpr int MN = 100000;
constexpr int NE = 3200000;

__device__ float g_he[MN];
__device__ int   g_i64flag;
__device__ float g_rsA[MN], g_rsB[MN];
__device__ __align__(256) s8 g_qhA[(size_t)MN * 256];
__device__ __align__(256) s8 g_qlA[(size_t)MN * 256];
__device__ __align__(256) s8 g_qhB[(size_t)MN * 256];
__device__ __align__(256) s8 g_qlB[(size_t)MN * 256];
__device__ __align__(256) s8 g_Wqh[7 * 65536];
__device__ __align__(256) s8 g_Wql[7 * 65536];
__device__ float g_ws[7 * 256];     // wmax/16256
__device__ float g_whe[7 * 256];
__device__ float g_bias[7 * 256];

// -------------------- PTX helpers -------------------------------------------
__device__ __forceinline__ uint32_t smem_u32(const void* p) {
    uint32_t a;
    asm("{ .reg .u64 t; cvta.to.shared.u64 t, %1; cvt.u32.u64 %0, t; }" : "=r"(a) : "l"(p));
    return a;
}
#define CP_ASYNC16(sm, g) \
    asm volatile("cp.async.cg.shared.global [%0], [%1], 16;" :: "r"(sm), "l"(g))
#define CP_COMMIT() asm volatile("cp.async.commit_group;" ::: "memory")
#define CP_WAIT(n)  asm volatile("cp.async.wait_group %0;" :: "n"(n) : "memory")
#define LDSM_X4(r0, r1, r2, r3, a) \
    asm volatile("ldmatrix.sync.aligned.m8n8.x4.shared.b16 {%0,%1,%2,%3}, [%4];" \
        : "=r"(r0), "=r"(r1), "=r"(r2), "=r"(r3) : "r"(a))

__device__ __forceinline__ void mma_s8(int* d, const uint32_t* a, const uint32_t* b) {
    asm("mma.sync.aligned.m16n8k32.row.col.s32.s8.s8.s32 "
        "{%0,%1,%2,%3}, {%4,%5,%6,%7}, {%8,%9}, {%0,%1,%2,%3};"
        : "+r"(d[0]), "+r"(d[1]), "+r"(d[2]), "+r"(d[3])
        : "r"(a[0]), "r"(a[1]), "r"(a[2]), "r"(a[3]), "r"(b[0]), "r"(b[1]));
}

__device__ __forceinline__ void quant2(float q, int& h, int& l) {
    float fh = rintf(q * 0.0078125f);          // q/128
    h = (int)fh;
    l = (int)rintf(fmaf(fh, -128.0f, q));
}

// -------------------- small kernels -----------------------------------------
__global__ void k_init(const void* __restrict__ dst_raw) {
    int i = blockIdx.x * blockDim.x + threadIdx.x;
    if (i < MN) g_he[i] = 0.0f;
    if (i == 0) {
        const long long* p = (const long long*)dst_raw;
        int is64 = 1;
        #pragma unroll
        for (int j = 0; j < 4; ++j) {
            long long v = p[j];
            if (v < 0 || v >= (long long)MN) is64 = 0;
        }
        g_i64flag = is64;
    }
}

__global__ void k_scatter(const float* __restrict__ ef, const void* __restrict__ dst_raw) {
    int i = blockIdx.x * blockDim.x + threadIdx.x;
    if (i >= NE) return;
    int d = g_i64flag ? (int)((const long long*)dst_raw)[i] : ((const int*)dst_raw)[i];
    atomicAdd(&g_he[d], ef[i]);
}

struct WPtrs { const float* W[7]; const float* B[7]; };

// one block per (n, layer): amax + quantize one weight row
__global__ void k_packw_all(WPtrs wp) {
    __shared__ float red[4];
    const int layer = blockIdx.y;
    const int n = blockIdx.x;
    const int tid = threadIdx.x;             // 128
    const int K = (layer == 0) ? 128 : 256;
    const int has_he = (layer < 6) ? 1 : 0;
    const int ld = K + has_he;
    const float* W = wp.W[layer];
    float m = 0.0f;
    for (int k = tid; k < K; k += 128) m = fmaxf(m, fabsf(W[(size_t)n * ld + k]));
    #pragma unroll
    for (int o = 16; o; o >>= 1) m = fmaxf(m, __shfl_xor_sync(0xffffffffu, m, o));
    if ((tid & 31) == 0) red[tid >> 5] = m;
    __syncthreads();
    m = fmaxf(fmaxf(red[0], red[1]), fmaxf(red[2], red[3]));
    m = fmaxf(m, 1e-20f);
    const float sq = 16256.0f / m;
    s8* qh = g_Wqh + layer * 65536 + n * K;
    s8* ql = g_Wql + layer * 65536 + n * K;
    for (int k = tid; k < K; k += 128) {
        int h, l;
        quant2(W[(size_t)n * ld + k] * sq, h, l);
        qh[k] = (s8)h; ql[k] = (s8)l;
    }
    if (tid == 0) {
        g_ws[layer * 256 + n]   = m * (1.0f / 16256.0f);
        g_whe[layer * 256 + n]  = has_he ? W[(size_t)n * ld + K] : 0.0f;
        g_bias[layer * 256 + n] = wp.B[layer][n];
    }
}

// quantize node_feat [MN,128] -> planes (stride 128) + rsA. warp per row.
__global__ void k_quant128(const float* __restrict__ A) {
    int row  = blockIdx.x * 8 + (threadIdx.x >> 5);
    int lane = threadIdx.x & 31;
    if (row >= MN) return;
    float4 v = *(const float4*)(A + (size_t)row * 128 + lane * 4);
    float m = fmaxf(fmaxf(fabsf(v.x), fabsf(v.y)), fmaxf(fabsf(v.z), fabsf(v.w)));
    #pragma unroll
    for (int o = 16; o; o >>= 1) m = fmaxf(m, __shfl_xor_sync(0xffffffffu, m, o));
    m = fmaxf(m, 1e-20f);
    const float sq = 16256.0f / m;
    uint32_t ph = 0, pl = 0;
    float vv[4] = {v.x, v.y, v.z, v.w};
    #pragma unroll
    for (int j = 0; j < 4; ++j) {
        int h, l;
        quant2(vv[j] * sq, h, l);
        ph |= (uint32_t)(h & 0xff) << (8 * j);
        pl |= (uint32_t)(l & 0xff) << (8 * j);
    }
    *(uint32_t*)(g_qhA + (size_t)row * 128 + lane * 4) = ph;
    *(uint32_t*)(g_qlA + (size_t)row * 128 + lane * 4) = pl;
    if (lane == 0) g_rsA[row] = m;
}

// -------------------- IMMA GEMM + fused requant ------------------------------
// CTA 64m x 256n, 512 thr (16 warps: wm=wid&1 m32, wn=wid>>1 n32), BK=64.
// Stage 40KB: Ah 4K | Al 4K | Wh 16K | Wl 16K; 3 stages.
// Plane addr(r,c16) = ((c ^ (r&3))*NR + r)*16, NR=64(A)/256(W).
template<int K, bool HAS_HE>
__global__ __launch_bounds__(512, 1)
void k_mma_i8(const s8* __restrict__ Aqh, const s8* __restrict__ Aql,
              const float* __restrict__ rs_in,
              const s8* __restrict__ Wqh, const s8* __restrict__ Wql,
              const float* __restrict__ ws,
              const float* __restrict__ bias, const float* __restrict__ whe,
              const float* __restrict__ he,
              s8* __restrict__ Cqh, s8* __restrict__ Cql,
              float* __restrict__ rs_out, int M)
{
    constexpr int NKC = K / 64;
    constexpr uint32_t STAGE = 40960;
    extern __shared__ __align__(128) char smem[];
    const uint32_t sb = smem_u32(smem);

    const int tid  = threadIdx.x;
    const int lane = tid & 31;
    const int wid  = tid >> 5;
    const int wm   = wid & 1;
    const int wn   = wid >> 1;
    const int bm   = blockIdx.x * 64;

    // A loader: 1 transfer/thread
    const int apl = tid >> 8, arem = tid & 255;
    const int ar = arem >> 2, ac = arem & 3;
    const int arow = min(bm + ar, M - 1);
    const s8* gA = (apl ? Aql : Aqh) + (size_t)arow * K + ac * 16;
    const uint32_t sA = apl * 4096u + (uint32_t)(((ac ^ (ar & 3)) * 64 + ar) << 4);

    auto load_stage = [&](int slot, int kc) {
        const uint32_t base = sb + slot * STAGE;
        CP_ASYNC16(base + sA, gA + kc * 64);
        #pragma unroll
        for (int i = 0; i < 4; ++i) {
            int idx = tid + i * 512;
            int pl = idx >> 10, rem = idx & 1023;
            int r = rem >> 2, c = rem & 3;
            const s8* gw = (pl ? Wql : Wqh) + (size_t)r * K + kc * 64 + c * 16;
            CP_ASYNC16(base + 8192u + pl * 16384u +
                       (uint32_t)(((c ^ (r & 3)) * 256 + r) << 4), gw);
        }
    };

    int hh[2][4][4], xx[2][4][4];
    #pragma unroll
    for (int mt = 0; mt < 2; ++mt)
        #pragma unroll
        for (int ng = 0; ng < 4; ++ng)
            #pragma unroll
            for (int q = 0; q < 4; ++q) { hh[mt][ng][q] = 0; xx[mt][ng][q] = 0; }

    load_stage(0, 0); CP_COMMIT();
    if (NKC > 1) { load_stage(1, 1); CP_COMMIT(); }
    else CP_COMMIT();

    const int lr = lane & 15;
    const int lc = lane >> 4;

    #pragma unroll 1
    for (int kc = 0; kc < NKC; ++kc) {
        CP_WAIT(1);
        __syncthreads();
        if (kc + 2 < NKC) load_stage((kc + 2) % 3, kc + 2);
        CP_COMMIT();

        const uint32_t st = sb + (kc % 3) * STAGE;
        #pragma unroll
        for (int k32 = 0; k32 < 2; ++k32) {
            const int c0 = k32 * 2 + lc;
            uint32_t Ah[2][4], Al[2][4], Bt[4][2];
            #pragma unroll
            for (int mt = 0; mt < 2; ++mt) {
                const int r = wm * 32 + mt * 16 + lr;
                const uint32_t a0 = st + (uint32_t)((((c0 ^ (r & 3)) * 64 + r) << 4));
                LDSM_X4(Ah[mt][0], Ah[mt][1], Ah[mt][2], Ah[mt][3], a0);
                LDSM_X4(Al[mt][0], Al[mt][1], Al[mt][2], Al[mt][3], a0 + 4096u);
            }
            // W-hi: HH += Ah.Bh ; X += Al.Bh
            #pragma unroll
            for (int gp = 0; gp < 2; ++gp) {
                const int r = wn * 32 + gp * 16 + lr;
                const uint32_t b0 = st + 8192u + (uint32_t)((((c0 ^ (r & 3)) * 256 + r) << 4));
                uint32_t t0, t1, t2, t3;
                LDSM_X4(t0, t1, t2, t3, b0);
                Bt[2 * gp][0] = t0; Bt[2 * gp + 1][0] = t1;
                Bt[2 * gp][1] = t2; Bt[2 * gp + 1][1] = t3;
            }
            #pragma unroll
            for (int mt = 0; mt < 2; ++mt)
                #pragma unroll
                for (int ng = 0; ng < 4; ++ng)
                    mma_s8(hh[mt][ng], Ah[mt], Bt[ng]);
            #pragma unroll
            for (int mt = 0; mt < 2; ++mt)
                #pragma unroll
                for (int ng = 0; ng < 4; ++ng)
                    mma_s8(xx[mt][ng], Al[mt], Bt[ng]);
            // W-lo: X += Ah.Bl
            #pragma unroll
            for (int gp = 0; gp < 2; ++gp) {
                const int r = wn * 32 + gp * 16 + lr;
                const uint32_t b0 = st + 24576u + (uint32_t)((((c0 ^ (r & 3)) * 256 + r) << 4));
                uint32_t t0, t1, t2, t3;
                LDSM_X4(t0, t1, t2, t3, b0);
                Bt[2 * gp][0] = t0; Bt[2 * gp + 1][0] = t1;
                Bt[2 * gp][1] = t2; Bt[2 * gp + 1][1] = t3;
            }
            #pragma unroll
            for (int mt = 0; mt < 2; ++mt)
                #pragma unroll
                for (int ng = 0; ng < 4; ++ng)
                    mma_s8(xx[mt][ng], Ah[mt], Bt[ng]);
        }
    }

    // ---- epilogue: dequant + bias + he*whe + relu -> smem fp32 --------------
    CP_WAIT(0);
    __syncthreads();
    float* cs = (float*)smem;                 // 64 rows x 264 floats
    constexpr int CS = 264;

    float wsv[4][2], bv[4][2], wv[4][2];
    const int colq = (lane & 3) * 2;
    #pragma unroll
    for (int ng = 0; ng < 4; ++ng) {
        const int cg = wn * 32 + ng * 8 + colq;
        wsv[ng][0] = __ldg(&ws[cg]);     wsv[ng][1] = __ldg(&ws[cg + 1]);
        bv[ng][0]  = __ldg(&bias[cg]);   bv[ng][1]  = __ldg(&bias[cg + 1]);
        if (HAS_HE) { wv[ng][0] = __ldg(&whe[cg]); wv[ng][1] = __ldg(&whe[cg + 1]); }
    }
    #pragma unroll
    for (int mt = 0; mt < 2; ++mt) {
        #pragma unroll
        for (int h = 0; h < 2; ++h) {
            const int rl  = wm * 32 + mt * 16 + h * 8 + (lane >> 2);
            const int row = bm + rl;
            const float rsc = (row < M) ? __ldg(&rs_in[row]) * (1.0f / 16256.0f) : 0.0f;
            const float hv  = (HAS_HE && row < M) ? __ldg(&he[row]) : 0.0f;
            #pragma unroll
            for (int ng = 0; ng < 4; ++ng) {
                float r0 = fmaf(16384.0f, (float)hh[mt][ng][2 * h + 0], 128.0f * (float)xx[mt][ng][2 * h + 0]);
                float r1 = fmaf(16384.0f, (float)hh[mt][ng][2 * h + 1], 128.0f * (float)xx[mt][ng][2 * h + 1]);
                float v0 = fmaf(rsc * wsv[ng][0], r0, bv[ng][0]);
                float v1 = fmaf(rsc * wsv[ng][1], r1, bv[ng][1]);
                if (HAS_HE) { v0 = fmaf(hv, wv[ng][0], v0); v1 = fmaf(hv, wv[ng][1], v1); }
                *(float2*)&cs[rl * CS + wn * 32 + ng * 8 + colq] =
                    make_float2(fmaxf(v0, 0.0f), fmaxf(v1, 0.0f));
            }
        }
    }
    __syncthreads();

    // ---- fused requant: warp per 4 rows, lane covers 8 cols -----------------
    #pragma unroll
    for (int i = 0; i < 4; ++i) {
        const int rl  = wid * 4 + i;
        const int row = bm + rl;
        float4 a = *(const float4*)&cs[rl * CS + lane * 8];
        float4 b = *(const float4*)&cs[rl * CS + lane * 8 + 4];
        float m = fmaxf(fmaxf(fmaxf(a.x, a.y), fmaxf(a.z, a.w)),
                        fmaxf(fmaxf(b.x, b.y), fmaxf(b.z, b.w)));   // relu'd: >=0
        #pragma unroll
        for (int o = 16; o; o >>= 1) m = fmaxf(m, __shfl_xor_sync(0xffffffffu, m, o));
        m = fmaxf(m, 1e-20f);
        const float sq = 16256.0f / m;
        float vv[8] = {a.x, a.y, a.z, a.w, b.x, b.y, b.z, b.w};
        uint32_t ph0 = 0, ph1 = 0, pl0 = 0, pl1 = 0;
        #pragma unroll
        for (int j = 0; j < 4; ++j) {
            int h, l;
            quant2(vv[j] * sq, h, l);
            ph0 |= (uint32_t)(h & 0xff) << (8 * j);
            pl0 |= (uint32_t)(l & 0xff) << (8 * j);
            quant2(vv[4 + j] * sq, h, l);
            ph1 |= (uint32_t)(h & 0xff) << (8 * j);
            pl1 |= (uint32_t)(l & 0xff) << (8 * j);
        }
        if (row < M) {
            *(uint2*)(Cqh + (size_t)row * 256 + lane * 8) = make_uint2(ph0, ph1);
            *(uint2*)(Cql + (size_t)row * 256 + lane * 8) = make_uint2(pl0, pl1);
            if (lane == 0) rs_out[row] = m;
        }
    }
}

// -------------------- final GEMV ---------------------------------------------
__global__ void k_gemv(const s8* __restrict__ qh, const s8* __restrict__ ql,
                       const float* __restrict__ rs,
                       const float* __restrict__ w, const float* __restrict__ b,
                       float* __restrict__ out, int M) {
    __shared__ __align__(16) float wsm[256];
    int tid = threadIdx.x;
    wsm[tid] = w[tid];
    __syncthreads();
    int row  = blockIdx.x * 8 + (tid >> 5);
    int lane = tid & 31;
    if (row >= M) return;
    uint2 vh = *(const uint2*)(qh + (size_t)row * 256 + lane * 8);
    uint2 vl = *(const uint2*)(ql + (size_t)row * 256 + lane * 8);
    const s8* hb = (const s8*)&vh;           // signed! (aarch64 char is unsigned)
    const s8* lb = (const s8*)&vl;
    float s = 0.0f;
    #pragma unroll
    for (int j = 0; j < 8; ++j)
        s = fmaf(fmaf(128.0f, (float)hb[j], (float)lb[j]), wsm[lane * 8 + j], s);
    #pragma unroll
    for (int o = 16; o; o >>= 1) s += __shfl_down_sync(0xffffffffu, s, o);
    if (lane == 0) out[row] = fmaf(s, __ldg(&rs[row]) * (1.0f / 16256.0f), b[0]);
}

// ---------------------------------------------------------------------------
extern "C" void kernel_launch(void* const* d_in, const int* in_sizes, int n_in,
                              void* d_out, int out_size) {
    const float* node_feat = (const float*)d_in[0];
    const float* edge_feat = (const float*)d_in[1];
    const void*  edge_dst  = d_in[2];
    WPtrs wp;
    for (int l = 0; l < 7; ++l) {
        wp.W[l] = (const float*)d_in[3 + 2 * l];
        wp.B[l] = (const float*)d_in[4 + 2 * l];
    }
    const float* Wr3 = (const float*)d_in[17];
    const float* br3 = (const float*)d_in[18];
    float* out = (float*)d_out;

    void* p;
    cudaGetSymbolAddress(&p, g_he);   float* he  = (float*)p;
    cudaGetSymbolAddress(&p, g_rsA);  float* rsA = (float*)p;
    cudaGetSymbolAddress(&p, g_rsB);  float* rsB = (float*)p;
    cudaGetSymbolAddress(&p, g_qhA);  s8* qhA = (s8*)p;
    cudaGetSymbolAddress(&p, g_qlA);  s8* qlA = (s8*)p;
    cudaGetSymbolAddress(&p, g_qhB);  s8* qhB = (s8*)p;
    cudaGetSymbolAddress(&p, g_qlB);  s8* qlB = (s8*)p;
    cudaGetSymbolAddress(&p, g_Wqh);  s8* Wqh = (s8*)p;
    cudaGetSymbolAddress(&p, g_Wql);  s8* Wql = (s8*)p;
    cudaGetSymbolAddress(&p, g_ws);   float* ws   = (float*)p;
    cudaGetSymbolAddress(&p, g_whe);  float* whe  = (float*)p;
    cudaGetSymbolAddress(&p, g_bias); float* bias = (float*)p;

    const int SMEM_DYN = 3 * 40960;   // 120KB
    cudaFuncSetAttribute(k_mma_i8<128, true >, cudaFuncAttributeMaxDynamicSharedMemorySize, SMEM_DYN);
    cudaFuncSetAttribute(k_mma_i8<256, true >, cudaFuncAttributeMaxDynamicSharedMemorySize, SMEM_DYN);
    cudaFuncSetAttribute(k_mma_i8<256, false>, cudaFuncAttributeMaxDynamicSharedMemorySize, SMEM_DYN);

    const int G = (MN + 63) / 64;     // 1563

    // #1..#4
    k_init<<<(MN + 255) / 256, 256>>>(edge_dst);
    k_scatter<<<(NE + 255) / 256, 256>>>(edge_feat, edge_dst);
    { dim3 g(256, 7); k_packw_all<<<g, 128>>>(wp); }
    k_quant128<<<(MN + 7) / 8, 256>>>(node_feat);
    // #5..#11: 7 layers (ncu samples #7 = layer 2)
    k_mma_i8<128, true ><<<G, 512, SMEM_DYN>>>(qhA, qlA, rsA, Wqh,             Wql,             ws,        bias,        whe,        he, qhB, qlB, rsB, MN);
    k_mma_i8<256, true ><<<G, 512, SMEM_DYN>>>(qhB, qlB, rsB, Wqh + 1 * 65536, Wql + 1 * 65536, ws + 256,  bias + 256,  whe + 256,  he, qhA, qlA, rsA, MN);
    k_mma_i8<256, true ><<<G, 512, SMEM_DYN>>>(qhA, qlA, rsA, Wqh + 2 * 65536, Wql + 2 * 65536, ws + 512,  bias + 512,  whe + 512,  he, qhB, qlB, rsB, MN);
    k_mma_i8<256, true ><<<G, 512, SMEM_DYN>>>(qhB, qlB, rsB, Wqh + 3 * 65536, Wql + 3 * 65536, ws + 768,  bias + 768,  whe + 768,  he, qhA, qlA, rsA, MN);
    k_mma_i8<256, true ><<<G, 512, SMEM_DYN>>>(qhA, qlA, rsA, Wqh + 4 * 65536, Wql + 4 * 65536, ws + 1024, bias + 1024, whe + 1024, he, qhB, qlB, rsB, MN);
    k_mma_i8<256, true ><<<G, 512, SMEM_DYN>>>(qhB, qlB, rsB, Wqh + 5 * 65536, Wql + 5 * 65536, ws + 1280, bias + 1280, whe + 1280, he, qhA, qlA, rsA, MN);
    k_mma_i8<256, false><<<G, 512, SMEM_DYN>>>(qhA, qlA, rsA, Wqh + 6 * 65536, Wql + 6 * 65536, ws + 1536, bias + 1536, nullptr,    nullptr, qhB, qlB, rsB, MN);
    // #12
    k_gemv<<<(MN + 7) / 8, 256>>>(qhB, qlB, rsB, Wr3, br3, out, MN);
}

// round 11
// speedup vs baseline: 2.5684x; 2.5684x over previous
#include <cuda_runtime.h>
#include <cuda_fp16.h>
#include <cstdint>

// ---------------------------------------------------------------------------
// GraphSAGE forward (round 11): 2-pass fp16 HMMA chain.
// Fix vs round 10: epilogue staging row is 256B (128 fp16 cols), not 512B —
// r10 stores were clobbering the neighbor CTA's columns with stale smem.
//   acc(f32) += Aq*Wh ; acc += (Aq*2^-10)*(Wl*2^10)   (scales cancel exactly)
// ---------------------------------------------------------------------------

typedef unsigned int u32;
constexpr int MN = 100000;
constexpr int NE = 3200000;

__device__ float g_he[MN];
__device__ int   g_i64flag;
__device__ __align__(256) __half g_hA[(size_t)MN * 256];
__device__ __align__(256) __half g_hB[(size_t)MN * 256];
__device__ __align__(256) __half g_Wh[7 * 65536];
__device__ __align__(256) __half g_Wl[7 * 65536];   // (w - wh) * 1024
__device__ float g_whe[7 * 256];
__device__ float g_bias[7 * 256];

// -------------------- PTX helpers -------------------------------------------
__device__ __forceinline__ u32 smem_u32(const void* p) {
    u32 a;
    asm("{ .reg .u64 t; cvta.to.shared.u64 t, %1; cvt.u32.u64 %0, t; }" : "=r"(a) : "l"(p));
    return a;
}
#define CP_ASYNC16(sm, g) \
    asm volatile("cp.async.cg.shared.global [%0], [%1], 16;" :: "r"(sm), "l"(g))
#define CP_COMMIT() asm volatile("cp.async.commit_group;" ::: "memory")
#define CP_WAIT(n)  asm volatile("cp.async.wait_group %0;" :: "n"(n) : "memory")
#define LDSM_X4(r0, r1, r2, r3, a) \
    asm volatile("ldmatrix.sync.aligned.m8n8.x4.shared.b16 {%0,%1,%2,%3}, [%4];" \
        : "=r"(r0), "=r"(r1), "=r"(r2), "=r"(r3) : "r"(a))

__device__ __forceinline__ void mma_f16(float* d, const u32* a, const u32* b) {
    asm("mma.sync.aligned.m16n8k16.row.col.f32.f16.f16.f32 "
        "{%0,%1,%2,%3}, {%4,%5,%6,%7}, {%8,%9}, {%0,%1,%2,%3};"
        : "+f"(d[0]), "+f"(d[1]), "+f"(d[2]), "+f"(d[3])
        : "r"(a[0]), "r"(a[1]), "r"(a[2]), "r"(a[3]), "r"(b[0]), "r"(b[1]));
}

// -------------------- small kernels -----------------------------------------
__global__ void k_quant_init(const float* __restrict__ A, const void* __restrict__ dst_raw) {
    int i = blockIdx.x * blockDim.x + threadIdx.x;
    if (i == 0) {
        const long long* p = (const long long*)dst_raw;
        int is64 = 1;
        #pragma unroll
        for (int j = 0; j < 4; ++j) {
            long long v = p[j];
            if (v < 0 || v >= (long long)MN) is64 = 0;
        }
        g_i64flag = is64;
    }
    if (i < MN) g_he[i] = 0.0f;
    if (i < MN * 128) g_hA[i] = __float2half_rn(A[i]);
}

__global__ void k_scatter(const float* __restrict__ ef, const void* __restrict__ dst_raw) {
    int i = blockIdx.x * blockDim.x + threadIdx.x;
    if (i >= NE) return;
    int d = g_i64flag ? (int)((const long long*)dst_raw)[i] : ((const int*)dst_raw)[i];
    atomicAdd(&g_he[d], ef[i]);
}

struct WPtrs { const float* W[7]; const float* B[7]; };

__global__ void k_packw_all(WPtrs wp) {
    const int layer = blockIdx.y;
    const int n = blockIdx.x;
    const int tid = threadIdx.x;          // 128
    const int K = (layer == 0) ? 128 : 256;
    const int has_he = (layer < 6) ? 1 : 0;
    const int ld = K + has_he;
    const float* W = wp.W[layer];
    __half* wh = g_Wh + layer * 65536 + n * K;
    __half* wl = g_Wl + layer * 65536 + n * K;
    for (int k = tid; k < K; k += 128) {
        float w = W[(size_t)n * ld + k];
        __half h = __float2half_rn(w);
        wh[k] = h;
        wl[k] = __float2half_rn((w - __half2float(h)) * 1024.0f);
    }
    if (tid == 0) {
        g_whe[layer * 256 + n]  = has_he ? W[(size_t)n * ld + K] : 0.0f;
        g_bias[layer * 256 + n] = wp.B[layer][n];
    }
}

// -------------------- 2-pass fp16 HMMA GEMM ----------------------------------
// C[M,256] = relu(A @ W^T + bias + he ⊗ whe). CTA 128m x 128n, 8 warps
// (4m x 2n, warp 32x64), BK=32, 3-stage cp.async, 2 CTAs/SM.
// Stage 24KB: Aq 8K | Wh 8K | Wl 8K. Plane addr(r,c16)=((c^(r&3))*128+r)*16.
template<int K, bool HAS_HE>
__global__ __launch_bounds__(256, 2)
void k_mma(const __half* __restrict__ Aq,
           const __half* __restrict__ Wh, const __half* __restrict__ Wl,
           const float* __restrict__ bias, const float* __restrict__ whe,
           const float* __restrict__ he,
           __half* __restrict__ C, int M)
{
    constexpr int NKC = K / 32;
    constexpr u32 STAGE = 24576;
    extern __shared__ __align__(128) char smem[];
    const u32 sb = smem_u32(smem);

    const int tid  = threadIdx.x;
    const int lane = tid & 31;
    const int wid  = tid >> 5;
    const int wm   = wid & 3;
    const int wn   = wid >> 2;
    const int bm   = blockIdx.y * 128;
    const int bn   = blockIdx.x * 128;

    // loader: slots s = tid, tid+256 ; r = s>>2, c = s&3
    const int r0 = tid >> 2,          c0 = tid & 3;
    const int r1 = (tid + 256) >> 2,  c1 = tid & 3;
    const __half* gA0 = Aq + (size_t)min(bm + r0, M - 1) * K + c0 * 8;
    const __half* gA1 = Aq + (size_t)min(bm + r1, M - 1) * K + c1 * 8;
    const __half* gH0 = Wh + (size_t)(bn + r0) * K + c0 * 8;
    const __half* gH1 = Wh + (size_t)(bn + r1) * K + c1 * 8;
    const __half* gL0 = Wl + (size_t)(bn + r0) * K + c0 * 8;
    const __half* gL1 = Wl + (size_t)(bn + r1) * K + c1 * 8;
    const u32 s0 = (u32)((((c0 ^ (r0 & 3)) << 7) + r0) << 4);
    const u32 s1 = (u32)((((c1 ^ (r1 & 3)) << 7) + r1) << 4);

    auto load_stage = [&](int slot, int kc) {
        const u32 base = sb + slot * STAGE;
        const int ko = kc * 32;
        CP_ASYNC16(base + s0,          gA0 + ko);
        CP_ASYNC16(base + s1,          gA1 + ko);
        CP_ASYNC16(base + 8192u + s0,  gH0 + ko);
        CP_ASYNC16(base + 8192u + s1,  gH1 + ko);
        CP_ASYNC16(base + 16384u + s0, gL0 + ko);
        CP_ASYNC16(base + 16384u + s1, gL1 + ko);
    };

    float acc[2][8][4];
    #pragma unroll
    for (int mt = 0; mt < 2; ++mt)
        #pragma unroll
        for (int ng = 0; ng < 8; ++ng)
            #pragma unroll
            for (int q = 0; q < 4; ++q) acc[mt][ng][q] = 0.0f;

    load_stage(0, 0); CP_COMMIT();
    load_stage(1, 1); CP_COMMIT();

    const int lr = lane & 15;
    const int lc = lane >> 4;
    const __half2 sc = __half2(__ushort_as_half((unsigned short)0x1400),
                               __ushort_as_half((unsigned short)0x1400)); // 2^-10

    #pragma unroll 1
    for (int kc = 0; kc < NKC; ++kc) {
        CP_WAIT(1);
        __syncthreads();
        if (kc + 2 < NKC) load_stage((kc + 2) % 3, kc + 2);
        CP_COMMIT();

        const u32 st = sb + (kc % 3) * STAGE;
        #pragma unroll
        for (int k16 = 0; k16 < 2; ++k16) {
            const int c0i = k16 * 2 + lc;
            u32 Af[2][4], A2[2][4], Bt[8][2];
            #pragma unroll
            for (int mt = 0; mt < 2; ++mt) {
                const int r = wm * 32 + mt * 16 + lr;
                const u32 a0 = st + (u32)(((((c0i ^ (r & 3)) << 7) + r) << 4));
                LDSM_X4(Af[mt][0], Af[mt][1], Af[mt][2], Af[mt][3], a0);
            }
            // ---- pass 1: W-hi ----------------------------------------------
            #pragma unroll
            for (int gp = 0; gp < 4; ++gp) {
                const int r = wn * 64 + gp * 16 + lr;
                const u32 b0 = st + 8192u + (u32)(((((c0i ^ (r & 3)) << 7) + r) << 4));
                u32 t0, t1, t2, t3;
                LDSM_X4(t0, t1, t2, t3, b0);
                Bt[2 * gp][0] = t0; Bt[2 * gp + 1][0] = t1;
                Bt[2 * gp][1] = t2; Bt[2 * gp + 1][1] = t3;
            }
            #pragma unroll
            for (int mt = 0; mt < 2; ++mt)
                #pragma unroll
                for (int ng = 0; ng < 8; ++ng)
                    mma_f16(acc[mt][ng], Af[mt], Bt[ng]);
            // scaled A for pass 2 (exact power-of-two scale, cancels Wl*2^10)
            #pragma unroll
            for (int mt = 0; mt < 2; ++mt)
                #pragma unroll
                for (int i = 0; i < 4; ++i) {
                    __half2 t = __hmul2(*(const __half2*)&Af[mt][i], sc);
                    A2[mt][i] = *(const u32*)&t;
                }
            // ---- pass 2: W-lo ----------------------------------------------
            #pragma unroll
            for (int gp = 0; gp < 4; ++gp) {
                const int r = wn * 64 + gp * 16 + lr;
                const u32 b0 = st + 16384u + (u32)(((((c0i ^ (r & 3)) << 7) + r) << 4));
                u32 t0, t1, t2, t3;
                LDSM_X4(t0, t1, t2, t3, b0);
                Bt[2 * gp][0] = t0; Bt[2 * gp + 1][0] = t1;
                Bt[2 * gp][1] = t2; Bt[2 * gp + 1][1] = t3;
            }
            #pragma unroll
            for (int mt = 0; mt < 2; ++mt)
                #pragma unroll
                for (int ng = 0; ng < 8; ++ng)
                    mma_f16(acc[mt][ng], A2[mt], Bt[ng]);
        }
    }

    // ---- epilogue: bias + he*whe + relu -> fp16, smem-staged stores ---------
    CP_WAIT(0);
    __syncthreads();
    constexpr u32 ROWB = 272;                 // 256B data + 16B pad per row

    float bv[8][2], wv[8][2];
    const int colq = (lane & 3) * 2;
    #pragma unroll
    for (int ng = 0; ng < 8; ++ng) {
        const int cg = bn + wn * 64 + ng * 8 + colq;
        bv[ng][0] = __ldg(&bias[cg]);
        bv[ng][1] = __ldg(&bias[cg + 1]);
        if (HAS_HE) {
            wv[ng][0] = __ldg(&whe[cg]);
            wv[ng][1] = __ldg(&whe[cg + 1]);
        }
    }
    #pragma unroll
    for (int mt = 0; mt < 2; ++mt) {
        #pragma unroll
        for (int h = 0; h < 2; ++h) {
            const int rl  = wm * 32 + mt * 16 + h * 8 + (lane >> 2);
            const int row = bm + rl;
            const float hv = (HAS_HE && row < M) ? __ldg(&he[row]) : 0.0f;
            #pragma unroll
            for (int ng = 0; ng < 8; ++ng) {
                float v0 = acc[mt][ng][2 * h + 0] + bv[ng][0];
                float v1 = acc[mt][ng][2 * h + 1] + bv[ng][1];
                if (HAS_HE) { v0 = fmaf(hv, wv[ng][0], v0); v1 = fmaf(hv, wv[ng][1], v1); }
                __half2 o = __floats2half2_rn(fmaxf(v0, 0.0f), fmaxf(v1, 0.0f));
                *(__half2*)(smem + rl * ROWB + (u32)(wn * 64 + ng * 8 + colq) * 2) = o;
            }
        }
    }
    __syncthreads();

    // coalesced stores: 16 lanes x 16B cover the CTA's 128 fp16 columns
    const int seg = tid & 15;
    const int rr  = tid >> 4;                 // 0..15
    #pragma unroll
    for (int i = 0; i < 8; ++i) {
        const int rl  = rr + i * 16;
        const int row = bm + rl;
        if (row < M)
            *(uint4*)(C + (size_t)row * 256 + bn + seg * 8) =
                *(const uint4*)(smem + rl * ROWB + seg * 16);
    }
}

// -------------------- final GEMV ---------------------------------------------
__global__ void k_gemv(const __half* __restrict__ A,
                       const float* __restrict__ w, const float* __restrict__ b,
                       float* __restrict__ out, int M) {
    __shared__ __align__(16) float wsm[256];
    int tid = threadIdx.x;
    wsm[tid] = w[tid];
    __syncthreads();
    int row  = blockIdx.x * 8 + (tid >> 5);
    int lane = tid & 31;
    if (row >= M) return;
    uint4 v = *(const uint4*)(A + (size_t)row * 256 + lane * 8);
    const __half2* hp = (const __half2*)&v;
    float s = 0.0f;
    #pragma unroll
    for (int q = 0; q < 4; ++q) {
        float2 f = __half22float2(hp[q]);
        s = fmaf(f.x, wsm[lane * 8 + 2 * q], s);
        s = fmaf(f.y, wsm[lane * 8 + 2 * q + 1], s);
    }
    #pragma unroll
    for (int o = 16; o; o >>= 1) s += __shfl_down_sync(0xffffffffu, s, o);
    if (lane == 0) out[row] = s + b[0];
}

// ---------------------------------------------------------------------------
extern "C" void kernel_launch(void* const* d_in, const int* in_sizes, int n_in,
                              void* d_out, int out_size) {
    const float* node_feat = (const float*)d_in[0];
    const float* edge_feat = (const float*)d_in[1];
    const void*  edge_dst  = d_in[2];
    WPtrs wp;
    for (int l = 0; l < 7; ++l) {
        wp.W[l] = (const float*)d_in[3 + 2 * l];
        wp.B[l] = (const float*)d_in[4 + 2 * l];
    }
    const float* Wr3 = (const float*)d_in[17];
    const float* br3 = (const float*)d_in[18];
    float* out = (float*)d_out;

    void* p;
    cudaGetSymbolAddress(&p, g_he);   float* he = (float*)p;
    cudaGetSymbolAddress(&p, g_hA);   __half* hA = (__half*)p;
    cudaGetSymbolAddress(&p, g_hB);   __half* hB = (__half*)p;
    cudaGetSymbolAddress(&p, g_Wh);   __half* Wh = (__half*)p;
    cudaGetSymbolAddress(&p, g_Wl);   __half* Wl = (__half*)p;
    cudaGetSymbolAddress(&p, g_whe);  float* whe  = (float*)p;
    cudaGetSymbolAddress(&p, g_bias); float* bias = (float*)p;

    const int SMEM_DYN = 3 * 24576;   // 72KB
    cudaFuncSetAttribute(k_mma<128, true >, cudaFuncAttributeMaxDynamicSharedMemorySize, SMEM_DYN);
    cudaFuncSetAttribute(k_mma<256, true >, cudaFuncAttributeMaxDynamicSharedMemorySize, SMEM_DYN);
    cudaFuncSetAttribute(k_mma<256, false>, cudaFuncAttributeMaxDynamicSharedMemorySize, SMEM_DYN);

    dim3 grid(2, (MN + 127) / 128);

    // #1: convert A + zero he + dtype detect
    k_quant_init<<<(MN * 128 + 255) / 256, 256>>>(node_feat, edge_dst);
    // #2: he scatter
    k_scatter<<<(NE + 255) / 256, 256>>>(edge_feat, edge_dst);
    // #3: pack all weights
    { dim3 g(256, 7); k_packw_all<<<g, 128>>>(wp); }
    // #4: layer 0  <-- ncu sample slot
    k_mma<128, true ><<<grid, 256, SMEM_DYN>>>(hA, Wh,             Wl,             bias,        whe,        he, hB, MN);
    k_mma<256, true ><<<grid, 256, SMEM_DYN>>>(hB, Wh + 1 * 65536, Wl + 1 * 65536, bias + 256,  whe + 256,  he, hA, MN);
    k_mma<256, true ><<<grid, 256, SMEM_DYN>>>(hA, Wh + 2 * 65536, Wl + 2 * 65536, bias + 512,  whe + 512,  he, hB, MN);
    k_mma<256, true ><<<grid, 256, SMEM_DYN>>>(hB, Wh + 3 * 65536, Wl + 3 * 65536, bias + 768,  whe + 768,  he, hA, MN);
    k_mma<256, true ><<<grid, 256, SMEM_DYN>>>(hA, Wh + 4 * 65536, Wl + 4 * 65536, bias + 1024, whe + 1024, he, hB, MN);
    k_mma<256, true ><<<grid, 256, SMEM_DYN>>>(hB, Wh + 5 * 65536, Wl + 5 * 65536, bias + 1280, whe + 1280, he, hA, MN);
    k_mma<256, false><<<grid, 256, SMEM_DYN>>>(hA, Wh + 6 * 65536, Wl + 6 * 65536, bias + 1536, nullptr,    nullptr, hB, MN);
    // final projection
    k_gemv<<<(MN + 7) / 8, 256>>>(hB, Wr3, br3, out, MN);
}